// round 6
// baseline (speedup 1.0000x reference)
#include <cuda_runtime.h>
#include <cuda_fp16.h>
#include <cstdint>

// ---------------------------------------------------------------------------
// BinaryConv2dBBCU_Down: avgpool2 -> +bias -> sign -> binary 3x3 conv -> RPReLU
// Conv operands are exactly +-1 and |partial sums| <= 1152 < 2048
//   => EXACT in f16 x f16 -> f16 MMA (fp16 accumulate, 2x the fp32-acc rate).
// 512-thread CTA covers 2 output rows (M=256, N=128): 16 warps/SM.
// ---------------------------------------------------------------------------

#define NB   8
#define CINC 128
#define COC  256
#define HPAD 130        // 128 pooled + 2 halo

// scratch (device globals: no allocation allowed)
__device__ __half g_actpad[(size_t)NB * HPAD * HPAD * CINC]; // channels-last signs
__device__ __half g_wb[(size_t)9 * COC * CINC];              // sign(W) per tap
__device__ float  g_wscale[COC];

// ---------------------------------------------------------------- halo zero
__global__ void halo_zero_kernel() {   // grid = NB*HPAD, 128 threads
    const int b = blockIdx.x / HPAD, pr = blockIdx.x % HPAD;
    uint32_t* row = reinterpret_cast<uint32_t*>(
        g_actpad + ((size_t)(b * HPAD + pr) * HPAD) * CINC);
    if (pr == 0 || pr == HPAD - 1) {
        for (int i = threadIdx.x; i < HPAD * 64; i += 128) row[i] = 0u;
    } else {
        if (threadIdx.x < 64) row[threadIdx.x] = 0u;                      // xp = 0
        else row[(HPAD - 1) * 64 + threadIdx.x - 64] = 0u;                // xp = 129
    }
}

// ------------------------------------------------ pool + bias + sign + pack
__global__ void __launch_bounds__(256) prep_kernel(const float* __restrict__ x,
                                                   const float* __restrict__ mbias) {
    const int y = blockIdx.x;        // pooled row 0..127
    const int b = blockIdx.y;
    const int tid = threadIdx.x, lane = tid & 31, wrp = tid >> 5;

    __shared__ __half st[128 * 130];   // [x][c], pitch 260B -> conflict-free

    for (int k = 0; k < 16; ++k) {
        const int c = wrp + 8 * k;
        const float* r0 = x + ((size_t)(b * CINC + c) * 256 + 2 * y) * 256;
        const float* r1 = r0 + 256;
        const float bias = __ldg(mbias + c);
#pragma unroll
        for (int xb = 0; xb < 4; ++xb) {
            const int xo = xb * 32 + lane;
            float2 u = *reinterpret_cast<const float2*>(r0 + 2 * xo);
            float2 v = *reinterpret_cast<const float2*>(r1 + 2 * xo);
            float p = (u.x + u.y + v.x + v.y) * 0.25f + bias;
            float sg = p > 0.f ? 1.f : (p < 0.f ? -1.f : 0.f);
            st[xo * 130 + c] = __float2half_rn(sg);
        }
    }
    __syncthreads();

    // interior row (y+1), xp = 1..128, 128 ch contiguous -> coalesced
    uint32_t* dst = reinterpret_cast<uint32_t*>(
        g_actpad + ((size_t)(b * HPAD + (y + 1)) * HPAD + 1) * CINC);
    const char* sp = reinterpret_cast<const char*>(st);
    for (int i = tid; i < 128 * 64; i += 256) {
        const int xr = i >> 6, wd = i & 63;
        dst[xr * 64 + wd] = *reinterpret_cast<const uint32_t*>(sp + xr * 260 + wd * 4);
    }
}

// ---------------------------------------------------- weight sign + scale
__global__ void wprep_kernel(const float* __restrict__ w) {
    const int oc = blockIdx.x, c = threadIdx.x;   // 256 blocks x 128 threads
    const float* wp = w + ((size_t)oc * CINC + c) * 9;
    float v[9];
    float s = 0.f;
#pragma unroll
    for (int i = 0; i < 9; ++i) { v[i] = wp[i]; s += fabsf(v[i]); }

    __shared__ float red[128];
    red[c] = s;
    __syncthreads();
    for (int o = 64; o > 0; o >>= 1) {
        if (c < o) red[c] += red[c + o];
        __syncthreads();
    }
    if (c == 0) g_wscale[oc] = red[0] * (1.f / 1152.f);

#pragma unroll
    for (int i = 0; i < 9; ++i) {   // i = dy*3+dx
        float sg = v[i] > 0.f ? 1.f : (v[i] < 0.f ? -1.f : 0.f);
        g_wb[((size_t)i * COC + oc) * CINC + c] = __float2half_rn(sg);
    }
}

// ---------------------------------------------------------------- conv GEMM
#define AP          272                     // smem pitch per 128-ch K-row (16B skew)
#define ACT_ENTRIES (4 * HPAD)              // 520 rows (4 padded rows)
#define ACT_SMEM    (ACT_ENTRIES * AP)      // 141440
#define W_SMEM      (128 * AP)              // 34816
#define CONV_SMEM   (ACT_SMEM + 2 * W_SMEM) // 211072

__device__ __forceinline__ void cpa16(uint32_t d, const void* s) {
    asm volatile("cp.async.cg.shared.global [%0], [%1], 16;\n" :: "r"(d), "l"(s));
}
__device__ __forceinline__ void cpa_commit() { asm volatile("cp.async.commit_group;\n"); }
__device__ __forceinline__ void cpa_wait0()  { asm volatile("cp.async.wait_group 0;\n"); }

__device__ __forceinline__ void ldsm4(uint32_t& r0, uint32_t& r1, uint32_t& r2, uint32_t& r3,
                                      uint32_t a) {
    asm volatile("ldmatrix.sync.aligned.m8n8.x4.shared.b16 {%0,%1,%2,%3},[%4];\n"
                 : "=r"(r0), "=r"(r1), "=r"(r2), "=r"(r3) : "r"(a));
}
// fp16 accumulate: D,C are 2x .f16x2 regs
__device__ __forceinline__ void mma16816h(uint32_t* c, const uint32_t* a, const uint32_t* b) {
    asm volatile("mma.sync.aligned.m16n8k16.row.col.f16.f16.f16.f16 "
                 "{%0,%1},{%2,%3,%4,%5},{%6,%7},{%0,%1};\n"
                 : "+r"(c[0]), "+r"(c[1])
                 : "r"(a[0]), "r"(a[1]), "r"(a[2]), "r"(a[3]), "r"(b[0]), "r"(b[1]));
}

__global__ void __launch_bounds__(512, 1) conv_kernel(
    float* __restrict__ out,
    const float* __restrict__ pb0, const float* __restrict__ alpha,
    const float* __restrict__ pb1)
{
    extern __shared__ char smem[];
    const int y0 = blockIdx.x * 2;            // first of 2 output rows
    const int b = blockIdx.y;
    const int nbase = blockIdx.z * 128;       // oc half
    const int tid = threadIdx.x, lane = tid & 31, wrp = tid >> 5;
    const int wm = wrp >> 1, wn = wrp & 1;    // warp grid 8(M) x 2(N)
    const int r = wm >> 2;                    // which of the 2 output rows
    const int xbase = (wm & 3) * 32;          // x-offset within the row

    const uint32_t sbase = (uint32_t)__cvta_generic_to_shared(smem);
    const uint32_t actS  = sbase;

    // --- async load: 4 padded act rows (contiguous 133120 B) ---
    const char* actg = reinterpret_cast<const char*>(
        g_actpad + (size_t)((b * HPAD + y0) * HPAD) * CINC);
    for (int i = tid; i < ACT_ENTRIES * 16; i += 512) {
        const int e = i >> 4, part = i & 15;
        cpa16(actS + e * AP + part * 16, actg + (size_t)e * 256 + part * 16);
    }
    // --- weights tap 0 into buffer 0 ---
    const char* wg = reinterpret_cast<const char*>(g_wb);
    {
        const char* src = wg + (size_t)nbase * 256;
        for (int i = tid; i < 128 * 16; i += 512) {
            const int o = i >> 4, part = i & 15;
            cpa16(sbase + ACT_SMEM + o * AP + part * 16, src + o * 256 + part * 16);
        }
    }
    cpa_commit();

    uint32_t acc[2][8][2];    // f16x2 accumulators (exact: integer sums <= 1152)
#pragma unroll
    for (int mt = 0; mt < 2; ++mt)
#pragma unroll
        for (int nt = 0; nt < 8; ++nt)
            acc[mt][nt][0] = acc[mt][nt][1] = 0u;

    // ldmatrix lane addressing
    const int lrow = lane & 7, grp = lane >> 3;
    const int rowin16 = (grp & 1) * 8 + lrow;   // A: m within m16 tile
    const int khA = (grp >> 1) * 16;            // A: k-half byte offset
    const int ntOff = (grp >> 1) * 8;           // B: which n8 tile of pair
    const int khB = (grp & 1) * 16;             // B: k-half byte offset

    for (int tap = 0; tap < 9; ++tap) {
        cpa_wait0();
        __syncthreads();

        const uint32_t wCur = sbase + ACT_SMEM + (tap & 1) * W_SMEM;
        if (tap < 8) {  // prefetch next tap weights into other buffer
            const uint32_t wNext = sbase + ACT_SMEM + ((tap + 1) & 1) * W_SMEM;
            const char* src = wg + (size_t)((tap + 1) * COC + nbase) * 256;
            for (int i = tid; i < 128 * 16; i += 512) {
                const int o = i >> 4, part = i & 15;
                cpa16(wNext + o * AP + part * 16, src + o * 256 + part * 16);
            }
            cpa_commit();
        }

        const int dy = tap / 3, dx = tap - dy * 3;
        uint32_t aAddr[2];
#pragma unroll
        for (int mt = 0; mt < 2; ++mt) {
            const int xx = xbase + mt * 16 + rowin16;
            const int e = (dy + r) * HPAD + xx + dx;
            aAddr[mt] = actS + e * AP + khA;
        }
        uint32_t bAddr[4];
#pragma unroll
        for (int p = 0; p < 4; ++p) {
            const int ocl = wn * 64 + p * 16 + ntOff + lrow;
            bAddr[p] = wCur + ocl * AP + khB;
        }

#pragma unroll
        for (int k0 = 0; k0 < 128; k0 += 16) {
            uint32_t a[2][4];
            ldsm4(a[0][0], a[0][1], a[0][2], a[0][3], aAddr[0] + k0 * 2);
            ldsm4(a[1][0], a[1][1], a[1][2], a[1][3], aAddr[1] + k0 * 2);
            uint32_t bf[8][2];
#pragma unroll
            for (int p = 0; p < 4; ++p) {
                uint32_t r0, r1, r2, r3;
                ldsm4(r0, r1, r2, r3, bAddr[p] + k0 * 2);
                bf[p * 2][0] = r0;     bf[p * 2][1] = r1;
                bf[p * 2 + 1][0] = r2; bf[p * 2 + 1][1] = r3;
            }
#pragma unroll
            for (int mt = 0; mt < 2; ++mt)
#pragma unroll
                for (int nt = 0; nt < 8; ++nt)
                    mma16816h(acc[mt][nt], a[mt], bf[nt]);
        }
    }

    // --- fused epilogue: exact f16->f32, scale, bias0, PReLU, bias1 ---
    const int mrow = lane >> 2, colp = (lane & 3) * 2;
    const int y = y0 + r;
#pragma unroll
    for (int nt = 0; nt < 8; ++nt) {
        const int oc = nbase + wn * 64 + nt * 8 + colp;
        const float s0 = g_wscale[oc],      s1 = g_wscale[oc + 1];
        const float c00 = __ldg(pb0 + oc),  c01 = __ldg(pb0 + oc + 1);
        const float a0 = __ldg(alpha + oc), a1 = __ldg(alpha + oc + 1);
        const float d0 = __ldg(pb1 + oc),   d1 = __ldg(pb1 + oc + 1);
        float* o0 = out + (((size_t)(b * COC + oc) * 128 + y) * 128);
        float* o1 = o0 + (size_t)128 * 128;
#pragma unroll
        for (int mt = 0; mt < 2; ++mt) {
            const int x0 = xbase + mt * 16 + mrow;
            // reg0: (row, col|col+1)   reg1: (row+8, col|col+1)
            float2 lo = __half22float2(*reinterpret_cast<__half2*>(&acc[mt][nt][0]));
            float2 hi = __half22float2(*reinterpret_cast<__half2*>(&acc[mt][nt][1]));
            float v;
            v = lo.x * s0 + c00; v = v >= 0.f ? v : v * a0; o0[x0]     = v + d0;
            v = lo.y * s1 + c01; v = v >= 0.f ? v : v * a1; o1[x0]     = v + d1;
            v = hi.x * s0 + c00; v = v >= 0.f ? v : v * a0; o0[x0 + 8] = v + d0;
            v = hi.y * s1 + c01; v = v >= 0.f ? v : v * a1; o1[x0 + 8] = v + d1;
        }
    }
}

// ---------------------------------------------------------------- launcher
extern "C" void kernel_launch(void* const* d_in, const int* in_sizes, int n_in,
                              void* d_out, int out_size) {
    const float* x   = (const float*)d_in[0];
    const float* wt  = (const float*)d_in[1];
    const float* mb  = (const float*)d_in[2];
    const float* pb0 = (const float*)d_in[3];
    const float* al  = (const float*)d_in[4];
    const float* pb1 = (const float*)d_in[5];
    float* out = (float*)d_out;

    cudaFuncSetAttribute(conv_kernel, cudaFuncAttributeMaxDynamicSharedMemorySize, CONV_SMEM);

    halo_zero_kernel<<<NB * HPAD, 128>>>();
    prep_kernel<<<dim3(128, NB), 256>>>(x, mb);
    wprep_kernel<<<COC, 128>>>(wt);
    conv_kernel<<<dim3(64, NB, 2), 512, CONV_SMEM>>>(out, pb0, al, pb1);
}

// round 7
// speedup vs baseline: 1.0462x; 1.0462x over previous
#include <cuda_runtime.h>
#include <cstdint>
#include <cmath>

// ---------------------------------------------------------------------------
// BinaryConv2dBBCU_Down: avgpool2 -> +bias -> sign -> binary 3x3 conv -> RPReLU
// Operands are exactly +-1 => exact in e4m3 MMA with f32 accumulate (|sum|<=1152).
// FP8 m16n8k32 halves MMA instruction count and LDSM traffic vs bf16 k16.
// ---------------------------------------------------------------------------

#define NB   8
#define CINC 128
#define COC  256
#define HPAD 130        // 128 pooled + 2 halo

#define E4M3_P1 0x38    // +1.0 in e4m3
#define E4M3_M1 0xB8    // -1.0 in e4m3

// scratch (device globals: no allocation allowed)
__device__ unsigned char g_act8[(size_t)NB * HPAD * HPAD * CINC]; // channels-last e4m3 signs
__device__ unsigned char g_wb8[(size_t)9 * COC * CINC];           // e4m3 sign(W), [tap][oc][c]
__device__ float         g_wscale[COC];

// ------------------------- pool + bias + sign + pack (+ halo zeroing fused)
__global__ void __launch_bounds__(256) prep_kernel(const float* __restrict__ x,
                                                   const float* __restrict__ mbias) {
    const int y = blockIdx.x;        // pooled row 0..127
    const int b = blockIdx.y;
    const int tid = threadIdx.x, lane = tid & 31, wrp = tid >> 5;

    __shared__ unsigned char st[128 * 136];   // [x][c], pitch 136B

    for (int k = 0; k < 16; ++k) {
        const int c = wrp + 8 * k;
        const float* r0 = x + ((size_t)(b * CINC + c) * 256 + 2 * y) * 256;
        const float* r1 = r0 + 256;
        const float bias = __ldg(mbias + c);
#pragma unroll
        for (int xb = 0; xb < 4; ++xb) {
            const int xo = xb * 32 + lane;
            float2 u = *reinterpret_cast<const float2*>(r0 + 2 * xo);
            float2 v = *reinterpret_cast<const float2*>(r1 + 2 * xo);
            float p = (u.x + u.y + v.x + v.y) * 0.25f + bias;
            st[xo * 136 + c] = p > 0.f ? (unsigned char)E4M3_P1
                                       : (p < 0.f ? (unsigned char)E4M3_M1 : (unsigned char)0);
        }
    }
    __syncthreads();

    // interior row (y+1), xp = 1..128, 128 ch contiguous -> coalesced
    uint32_t* dst = reinterpret_cast<uint32_t*>(
        g_act8 + ((size_t)(b * HPAD + (y + 1)) * HPAD + 1) * CINC);
    const char* sp = reinterpret_cast<const char*>(st);
    for (int i = tid; i < 128 * 32; i += 256) {
        const int xr = i >> 5, wd = i & 31;
        dst[xr * 32 + wd] = *reinterpret_cast<const uint32_t*>(sp + xr * 136 + wd * 4);
    }

    // fused halo zeroing
    uint32_t* base = reinterpret_cast<uint32_t*>(g_act8 + ((size_t)b * HPAD * HPAD) * CINC);
    if (y == 0) {        // padded row 0
        for (int i = tid; i < HPAD * 32; i += 256) base[i] = 0u;
    } else if (y == 127) { // padded row 129
        uint32_t* r129 = base + (size_t)129 * HPAD * 32;
        for (int i = tid; i < HPAD * 32; i += 256) r129[i] = 0u;
    }
    // column halos of row y+1: xp = 0 and xp = 129
    uint32_t* rowp = base + (size_t)(y + 1) * HPAD * 32;
    if (tid < 32) rowp[tid] = 0u;
    else if (tid < 64) rowp[129 * 32 + tid - 32] = 0u;
}

// ---------------------------------------------------- weight sign + scale
__global__ void wprep_kernel(const float* __restrict__ w) {
    const int oc = blockIdx.x, c = threadIdx.x;   // 256 blocks x 128 threads
    const float* wp = w + ((size_t)oc * CINC + c) * 9;
    float v[9];
    float s = 0.f;
#pragma unroll
    for (int i = 0; i < 9; ++i) { v[i] = wp[i]; s += fabsf(v[i]); }

    __shared__ float red[128];
    red[c] = s;
    __syncthreads();
    for (int o = 64; o > 0; o >>= 1) {
        if (c < o) red[c] += red[c + o];
        __syncthreads();
    }
    if (c == 0) g_wscale[oc] = red[0] * (1.f / 1152.f);

#pragma unroll
    for (int i = 0; i < 9; ++i) {   // i = dy*3+dx
        g_wb8[((size_t)i * COC + oc) * CINC + c] =
            v[i] > 0.f ? (unsigned char)E4M3_P1
                       : (v[i] < 0.f ? (unsigned char)E4M3_M1 : (unsigned char)0);
    }
}

// ---------------------------------------------------------------- conv GEMM (fp8)
#define AP          144                     // smem pitch per 128B K-row (16B skew)
#define ACT_ENTRIES (3 * HPAD)              // 390 rows
#define ACT_SMEM    (ACT_ENTRIES * AP)      // 56160
#define W_SMEM      (128 * AP)              // 18432
#define CONV_SMEM   (ACT_SMEM + 2 * W_SMEM) // 93024 -> 2 CTAs/SM

__device__ __forceinline__ void cpa16(uint32_t d, const void* s) {
    asm volatile("cp.async.cg.shared.global [%0], [%1], 16;\n" :: "r"(d), "l"(s));
}
__device__ __forceinline__ void cpa_commit() { asm volatile("cp.async.commit_group;\n"); }
__device__ __forceinline__ void cpa_wait0()  { asm volatile("cp.async.wait_group 0;\n"); }

__device__ __forceinline__ void ldsm4(uint32_t& r0, uint32_t& r1, uint32_t& r2, uint32_t& r3,
                                      uint32_t a) {
    asm volatile("ldmatrix.sync.aligned.m8n8.x4.shared.b16 {%0,%1,%2,%3},[%4];\n"
                 : "=r"(r0), "=r"(r1), "=r"(r2), "=r"(r3) : "r"(a));
}
__device__ __forceinline__ void mma16832f8(float* c, const uint32_t* a, const uint32_t* b) {
    asm volatile("mma.sync.aligned.m16n8k32.row.col.f32.e4m3.e4m3.f32 "
                 "{%0,%1,%2,%3},{%4,%5,%6,%7},{%8,%9},{%0,%1,%2,%3};\n"
                 : "+f"(c[0]), "+f"(c[1]), "+f"(c[2]), "+f"(c[3])
                 : "r"(a[0]), "r"(a[1]), "r"(a[2]), "r"(a[3]), "r"(b[0]), "r"(b[1]));
}

__global__ void __launch_bounds__(256, 2) conv_kernel(
    float* __restrict__ out,
    const float* __restrict__ pb0, const float* __restrict__ alpha,
    const float* __restrict__ pb1)
{
    extern __shared__ char smem[];
    const int y = blockIdx.x;                 // output row
    const int b = blockIdx.y;
    const int nbase = blockIdx.z * 128;       // oc half
    const int tid = threadIdx.x, lane = tid & 31, wrp = tid >> 5;
    const int wm = wrp >> 1, wn = wrp & 1;    // warp grid 4(M) x 2(N)

    const uint32_t sbase = (uint32_t)__cvta_generic_to_shared(smem);
    const uint32_t actS  = sbase;

    // --- async load: 3 padded act rows (contiguous 49920 B) ---
    const char* actg = reinterpret_cast<const char*>(
        g_act8 + (size_t)((b * HPAD + y) * HPAD) * CINC);
    for (int i = tid; i < ACT_ENTRIES * 8; i += 256) {
        const int e = i >> 3, part = i & 7;
        cpa16(actS + e * AP + part * 16, actg + e * 128 + part * 16);
    }
    // --- weights tap 0 into buffer 0 ---
    const char* wg = reinterpret_cast<const char*>(g_wb8);
    {
        const char* src = wg + (size_t)nbase * 128;
        for (int i = tid; i < 128 * 8; i += 256) {
            const int o = i >> 3, part = i & 7;
            cpa16(sbase + ACT_SMEM + o * AP + part * 16, src + o * 128 + part * 16);
        }
    }
    cpa_commit();

    float acc[2][8][4];
#pragma unroll
    for (int mt = 0; mt < 2; ++mt)
#pragma unroll
        for (int nt = 0; nt < 8; ++nt)
#pragma unroll
            for (int j = 0; j < 4; ++j) acc[mt][nt][j] = 0.f;

    // ldmatrix lane addressing (byte-granular layout validated in the s8 round;
    // b16 ldmatrix hands each lane 4 consecutive bytes = the 8-bit fragment layout)
    const int lrow = lane & 7, grp = lane >> 3;
    const int rowin16 = (grp & 1) * 8 + lrow;   // A: m within m16 tile
    const int khA = (grp >> 1) * 16;            // A: k-half byte offset within k32
    const int ntOff = (grp >> 1) * 8;           // B: which n8 tile of pair
    const int khB = (grp & 1) * 16;             // B: k-half byte offset within k32

    for (int tap = 0; tap < 9; ++tap) {
        cpa_wait0();
        __syncthreads();

        const uint32_t wCur = sbase + ACT_SMEM + (tap & 1) * W_SMEM;
        if (tap < 8) {  // prefetch next tap weights into other buffer
            const uint32_t wNext = sbase + ACT_SMEM + ((tap + 1) & 1) * W_SMEM;
            const char* src = wg + (size_t)((tap + 1) * COC + nbase) * 128;
            for (int i = tid; i < 128 * 8; i += 256) {
                const int o = i >> 3, part = i & 7;
                cpa16(wNext + o * AP + part * 16, src + o * 128 + part * 16);
            }
            cpa_commit();
        }

        const int dy = tap / 3, dx = tap - dy * 3;
        uint32_t aAddr[2];
#pragma unroll
        for (int mt = 0; mt < 2; ++mt) {
            const int xx = wm * 32 + mt * 16 + rowin16;
            const int e = dy * HPAD + xx + dx;
            aAddr[mt] = actS + e * AP + khA;
        }
        uint32_t bAddr[4];
#pragma unroll
        for (int p = 0; p < 4; ++p) {
            const int ocl = wn * 64 + p * 16 + ntOff + lrow;
            bAddr[p] = wCur + ocl * AP + khB;
        }

#pragma unroll
        for (int k0 = 0; k0 < 4; ++k0) {        // 4 k-steps of 32 bytes
            uint32_t a[2][4];
            ldsm4(a[0][0], a[0][1], a[0][2], a[0][3], aAddr[0] + k0 * 32);
            ldsm4(a[1][0], a[1][1], a[1][2], a[1][3], aAddr[1] + k0 * 32);
            uint32_t bf[8][2];
#pragma unroll
            for (int p = 0; p < 4; ++p) {
                uint32_t r0, r1, r2, r3;
                ldsm4(r0, r1, r2, r3, bAddr[p] + k0 * 32);
                bf[p * 2][0] = r0;     bf[p * 2][1] = r1;
                bf[p * 2 + 1][0] = r2; bf[p * 2 + 1][1] = r3;
            }
#pragma unroll
            for (int mt = 0; mt < 2; ++mt)
#pragma unroll
                for (int nt = 0; nt < 8; ++nt)
                    mma16832f8(acc[mt][nt], a[mt], bf[nt]);
        }
    }

    // --- fused epilogue: scale, bias0, PReLU, bias1 ---
    const int row = lane >> 2, colp = (lane & 3) * 2;
#pragma unroll
    for (int nt = 0; nt < 8; ++nt) {
        const int oc = nbase + wn * 64 + nt * 8 + colp;
        const float s0 = g_wscale[oc],      s1 = g_wscale[oc + 1];
        const float c00 = __ldg(pb0 + oc),  c01 = __ldg(pb0 + oc + 1);
        const float a0 = __ldg(alpha + oc), a1 = __ldg(alpha + oc + 1);
        const float d0 = __ldg(pb1 + oc),   d1 = __ldg(pb1 + oc + 1);
        float* o0 = out + (((size_t)(b * COC + oc) * 128 + y) * 128);
        float* o1 = o0 + (size_t)128 * 128;
#pragma unroll
        for (int mt = 0; mt < 2; ++mt) {
            const int x0 = wm * 32 + mt * 16 + row;
            float v;
            v = acc[mt][nt][0] * s0 + c00; v = v >= 0.f ? v : v * a0; o0[x0]     = v + d0;
            v = acc[mt][nt][1] * s1 + c01; v = v >= 0.f ? v : v * a1; o1[x0]     = v + d1;
            v = acc[mt][nt][2] * s0 + c00; v = v >= 0.f ? v : v * a0; o0[x0 + 8] = v + d0;
            v = acc[mt][nt][3] * s1 + c01; v = v >= 0.f ? v : v * a1; o1[x0 + 8] = v + d1;
        }
    }
}

// ---------------------------------------------------------------- launcher
extern "C" void kernel_launch(void* const* d_in, const int* in_sizes, int n_in,
                              void* d_out, int out_size) {
    const float* x   = (const float*)d_in[0];
    const float* wt  = (const float*)d_in[1];
    const float* mb  = (const float*)d_in[2];
    const float* pb0 = (const float*)d_in[3];
    const float* al  = (const float*)d_in[4];
    const float* pb1 = (const float*)d_in[5];
    float* out = (float*)d_out;

    cudaFuncSetAttribute(conv_kernel, cudaFuncAttributeMaxDynamicSharedMemorySize, CONV_SMEM);

    prep_kernel<<<dim3(128, NB), 256>>>(x, mb);
    wprep_kernel<<<COC, 128>>>(wt);
    conv_kernel<<<dim3(128, NB, 2), 256, CONV_SMEM>>>(out, pb0, al, pb1);
}

// round 8
// speedup vs baseline: 1.1362x; 1.0860x over previous
#include <cuda_runtime.h>
#include <cstdint>
#include <cmath>

// ---------------------------------------------------------------------------
// BinaryConv2dBBCU_Down: avgpool2 -> +bias -> sign -> binary 3x3 conv -> RPReLU
// Operands exactly +-1 => exact in e4m3 MMA, f32 accumulate (|sum|<=1152).
// Staging via cp.async.bulk (1 instr per act block / weight tap) kills the
// LDGSTS issue bottleneck that bounded all previous rounds.
// ---------------------------------------------------------------------------

#define NB   8
#define CINC 128
#define COC  256
#define HPAD 130        // 128 pooled + 2 halo

#define E4M3_P1 0x38
#define E4M3_M1 0xB8

#define AP       144                    // row pitch (gmem AND smem), 16B skew
#define ACT_ROW  (HPAD * AP)            // 18720 B per padded row
#define ACT_SMEM (3 * ACT_ROW)          // 56160
#define W_TAP    (128 * AP)             // 18432 per tap per nhalf
#define BAR_OFF  (ACT_SMEM + 2 * W_TAP) // 93024
#define SMEM_TOT (BAR_OFF + 32)         // 93056 -> 2 CTAs/SM

// scratch (device globals; pitched layouts match smem so bulk copies are linear)
__device__ __align__(256) unsigned char g_act8[(size_t)NB * HPAD * ACT_ROW / HPAD * HPAD]; // NB*HPAD rows * 18720? see below
// NOTE: proper size: NB * HPAD * ACT_ROW bytes would be rows^2; actual: [b][prow][entry*144]
__device__ __align__(256) unsigned char g_wb8[(size_t)2 * 9 * W_TAP];   // [nh][tap][oc][144]
__device__ float g_wscale[COC];

// g_act8 true extent: NB * HPAD * HPAD * 144 bytes
#define ACT_TOTAL ((size_t)NB * HPAD * HPAD * AP)

// ------------------------- pool + bias + sign + pack (+ halo zeroing fused)
__global__ void __launch_bounds__(256) prep_kernel(const float* __restrict__ x,
                                                   const float* __restrict__ mbias) {
    const int y = blockIdx.x;        // pooled row 0..127
    const int b = blockIdx.y;
    const int tid = threadIdx.x, lane = tid & 31, wrp = tid >> 5;

    __shared__ unsigned char st[128 * 136];   // [x][c], pitch 136B

    for (int k = 0; k < 16; ++k) {
        const int c = wrp + 8 * k;
        const float* r0 = x + ((size_t)(b * CINC + c) * 256 + 2 * y) * 256;
        const float* r1 = r0 + 256;
        const float bias = __ldg(mbias + c);
#pragma unroll
        for (int xb = 0; xb < 4; ++xb) {
            const int xo = xb * 32 + lane;
            float2 u = *reinterpret_cast<const float2*>(r0 + 2 * xo);
            float2 v = *reinterpret_cast<const float2*>(r1 + 2 * xo);
            float p = (u.x + u.y + v.x + v.y) * 0.25f + bias;
            st[xo * 136 + c] = p > 0.f ? (unsigned char)E4M3_P1
                                       : (p < 0.f ? (unsigned char)E4M3_M1 : (unsigned char)0);
        }
    }
    __syncthreads();

    // interior row (y+1), entries xp=1..128 at pitch 144
    unsigned char* rowbase = g_act8 + ((size_t)(b * HPAD + (y + 1)) * HPAD) * AP;
    uint32_t* dst = reinterpret_cast<uint32_t*>(rowbase);
    const char* sp = reinterpret_cast<const char*>(st);
    for (int i = tid; i < 128 * 32; i += 256) {
        const int xr = i >> 5, wd = i & 31;   // entry xr+1, word wd
        dst[(xr + 1) * 36 + wd] = *reinterpret_cast<const uint32_t*>(sp + xr * 136 + wd * 4);
    }

    // halos
    uint32_t* base = reinterpret_cast<uint32_t*>(g_act8 + ((size_t)b * HPAD * HPAD) * AP);
    if (y == 0) {          // padded row 0 (entire 18720 B)
        for (int i = tid; i < HPAD * 36; i += 256) base[i] = 0u;
    } else if (y == 127) { // padded row 129
        uint32_t* r129 = base + (size_t)129 * HPAD * 36;
        for (int i = tid; i < HPAD * 36; i += 256) r129[i] = 0u;
    }
    // column halos of row y+1: entries xp=0 and xp=129 (zero their 128 data bytes)
    uint32_t* rowp = base + (size_t)(y + 1) * HPAD * 36;
    if (tid < 32) rowp[tid] = 0u;
    else if (tid < 64) rowp[129 * 36 + (tid - 32)] = 0u;
}

// ---------------------------------------------------- weight sign + scale
__global__ void wprep_kernel(const float* __restrict__ w) {
    const int oc = blockIdx.x, c = threadIdx.x;   // 256 x 128
    const float* wp = w + ((size_t)oc * CINC + c) * 9;
    float v[9];
    float s = 0.f;
#pragma unroll
    for (int i = 0; i < 9; ++i) { v[i] = wp[i]; s += fabsf(v[i]); }

    __shared__ float red[128];
    red[c] = s;
    __syncthreads();
    for (int o = 64; o > 0; o >>= 1) {
        if (c < o) red[c] += red[c + o];
        __syncthreads();
    }
    if (c == 0) g_wscale[oc] = red[0] * (1.f / 1152.f);

    const int nh = oc >> 7, ocl = oc & 127;
#pragma unroll
    for (int i = 0; i < 9; ++i) {   // i = dy*3+dx
        g_wb8[((size_t)(nh * 9 + i) * 128 + ocl) * AP + c] =
            v[i] > 0.f ? (unsigned char)E4M3_P1
                       : (v[i] < 0.f ? (unsigned char)E4M3_M1 : (unsigned char)0);
    }
}

// ------------------------------------------------------------- PTX helpers
__device__ __forceinline__ void bulkcp(uint32_t dst, const void* src, uint32_t bytes,
                                       uint32_t mbar) {
    asm volatile("cp.async.bulk.shared::cta.global.mbarrier::complete_tx::bytes "
                 "[%0], [%1], %2, [%3];"
                 :: "r"(dst), "l"(src), "r"(bytes), "r"(mbar) : "memory");
}
__device__ __forceinline__ void mbar_init(uint32_t a, uint32_t cnt) {
    asm volatile("mbarrier.init.shared.b64 [%0], %1;" :: "r"(a), "r"(cnt) : "memory");
}
__device__ __forceinline__ void mbar_expect(uint32_t a, uint32_t bytes) {
    asm volatile("mbarrier.arrive.expect_tx.shared.b64 _, [%0], %1;"
                 :: "r"(a), "r"(bytes) : "memory");
}
__device__ __forceinline__ void mbar_arrive(uint32_t a) {
    asm volatile("mbarrier.arrive.shared.b64 _, [%0];" :: "r"(a) : "memory");
}
__device__ __forceinline__ void mbar_wait(uint32_t a, uint32_t parity) {
    asm volatile(
        "{\n\t.reg .pred P1;\n\t"
        "WAIT_%=:\n\t"
        "mbarrier.try_wait.parity.acquire.cta.shared::cta.b64 P1, [%0], %1, 0x989680;\n\t"
        "@P1 bra.uni DONE_%=;\n\t"
        "bra.uni WAIT_%=;\n\t"
        "DONE_%=:\n\t}"
        :: "r"(a), "r"(parity) : "memory");
}
__device__ __forceinline__ void ldsm4(uint32_t& r0, uint32_t& r1, uint32_t& r2, uint32_t& r3,
                                      uint32_t a) {
    asm volatile("ldmatrix.sync.aligned.m8n8.x4.shared.b16 {%0,%1,%2,%3},[%4];\n"
                 : "=r"(r0), "=r"(r1), "=r"(r2), "=r"(r3) : "r"(a));
}
__device__ __forceinline__ void mma16832f8(float* c, const uint32_t* a, const uint32_t* b) {
    asm volatile("mma.sync.aligned.m16n8k32.row.col.f32.e4m3.e4m3.f32 "
                 "{%0,%1,%2,%3},{%4,%5,%6,%7},{%8,%9},{%0,%1,%2,%3};\n"
                 : "+f"(c[0]), "+f"(c[1]), "+f"(c[2]), "+f"(c[3])
                 : "r"(a[0]), "r"(a[1]), "r"(a[2]), "r"(a[3]), "r"(b[0]), "r"(b[1]));
}

// ---------------------------------------------------------------- conv GEMM
__global__ void __launch_bounds__(256, 2) conv_kernel(
    float* __restrict__ out,
    const float* __restrict__ pb0, const float* __restrict__ alpha,
    const float* __restrict__ pb1)
{
    extern __shared__ char smem[];
    const int y = blockIdx.x;                 // output row
    const int b = blockIdx.y;
    const int nh = blockIdx.z;                // oc half
    const int nbase = nh * 128;
    const int tid = threadIdx.x, lane = tid & 31, wrp = tid >> 5;
    const int wm = wrp >> 1, wn = wrp & 1;    // warp grid 4(M) x 2(N)

    const uint32_t sbase = (uint32_t)__cvta_generic_to_shared(smem);
    const uint32_t FULL0 = sbase + BAR_OFF,      FULL1 = sbase + BAR_OFF + 8;
    const uint32_t EMPT0 = sbase + BAR_OFF + 16, EMPT1 = sbase + BAR_OFF + 24;

    if (tid == 0) {
        mbar_init(FULL0, 1);   mbar_init(FULL1, 1);
        mbar_init(EMPT0, 256); mbar_init(EMPT1, 256);
    }
    __syncthreads();

    const unsigned char* actg = g_act8 + (size_t)((b * HPAD + y) * HPAD) * AP;
    const unsigned char* wsrc = g_wb8 + (size_t)nh * 9 * W_TAP;

    if (tid == 0) {
        mbar_expect(FULL0, ACT_SMEM + W_TAP);
        bulkcp(sbase, actg, ACT_SMEM, FULL0);                       // 3 act rows
        bulkcp(sbase + ACT_SMEM, wsrc, W_TAP, FULL0);               // tap 0
        mbar_expect(FULL1, W_TAP);
        bulkcp(sbase + ACT_SMEM + W_TAP, wsrc + W_TAP, W_TAP, FULL1); // tap 1
    }

    float acc[2][8][4];
#pragma unroll
    for (int mt = 0; mt < 2; ++mt)
#pragma unroll
        for (int nt = 0; nt < 8; ++nt)
#pragma unroll
            for (int j = 0; j < 4; ++j) acc[mt][nt][j] = 0.f;

    // ldmatrix lane addressing (byte-level layout validated in s8/fp8 rounds)
    const int lrow = lane & 7, grp = lane >> 3;
    const int rowin16 = (grp & 1) * 8 + lrow;   // A: m within m16 tile
    const int khA = (grp >> 1) * 16;            // A: k-half byte offset within k32
    const int ntOff = (grp >> 1) * 8;           // B: which n8 tile of pair
    const int khB = (grp & 1) * 16;             // B: k-half byte offset within k32

    for (int tap = 0; tap < 9; ++tap) {
        const int buf = tap & 1;
        const uint32_t ph = (tap >> 1) & 1;
        mbar_wait(buf ? FULL1 : FULL0, ph);

        const uint32_t wCur = sbase + ACT_SMEM + buf * W_TAP;
        const int dy = tap / 3, dx = tap - dy * 3;
        uint32_t aAddr[2];
#pragma unroll
        for (int mt = 0; mt < 2; ++mt) {
            const int xx = wm * 32 + mt * 16 + rowin16;
            const int e = dy * HPAD + xx + dx;
            aAddr[mt] = sbase + e * AP + khA;
        }
        uint32_t bAddr[4];
#pragma unroll
        for (int p = 0; p < 4; ++p) {
            const int ocl = wn * 64 + p * 16 + ntOff + lrow;
            bAddr[p] = wCur + ocl * AP + khB;
        }

#pragma unroll
        for (int k0 = 0; k0 < 4; ++k0) {        // 4 k-steps of 32 bytes
            uint32_t a[2][4];
            ldsm4(a[0][0], a[0][1], a[0][2], a[0][3], aAddr[0] + k0 * 32);
            ldsm4(a[1][0], a[1][1], a[1][2], a[1][3], aAddr[1] + k0 * 32);
            uint32_t bf[8][2];
#pragma unroll
            for (int p = 0; p < 4; ++p) {
                uint32_t r0, r1, r2, r3;
                ldsm4(r0, r1, r2, r3, bAddr[p] + k0 * 32);
                bf[p * 2][0] = r0;     bf[p * 2][1] = r1;
                bf[p * 2 + 1][0] = r2; bf[p * 2 + 1][1] = r3;
            }
#pragma unroll
            for (int mt = 0; mt < 2; ++mt)
#pragma unroll
                for (int nt = 0; nt < 8; ++nt)
                    mma16832f8(acc[mt][nt], a[mt], bf[nt]);
        }

        // weight buffer consumed (all LDSMs for this tap are done)
        if (tap < 7) {
            mbar_arrive(buf ? EMPT1 : EMPT0);
            if (tid == 0) {
                mbar_wait(buf ? EMPT1 : EMPT0, ph);   // buffer fully free
                mbar_expect(buf ? FULL1 : FULL0, W_TAP);
                bulkcp(wCur, wsrc + (size_t)(tap + 2) * W_TAP, W_TAP,
                       buf ? FULL1 : FULL0);
            }
        }
    }

    // --- fused epilogue: scale, bias0, PReLU, bias1 ---
    const int row = lane >> 2, colp = (lane & 3) * 2;
#pragma unroll
    for (int nt = 0; nt < 8; ++nt) {
        const int oc = nbase + wn * 64 + nt * 8 + colp;
        const float s0 = g_wscale[oc],      s1 = g_wscale[oc + 1];
        const float c00 = __ldg(pb0 + oc),  c01 = __ldg(pb0 + oc + 1);
        const float a0 = __ldg(alpha + oc), a1 = __ldg(alpha + oc + 1);
        const float d0 = __ldg(pb1 + oc),   d1 = __ldg(pb1 + oc + 1);
        float* o0 = out + (((size_t)(b * COC + oc) * 128 + y) * 128);
        float* o1 = o0 + (size_t)128 * 128;
#pragma unroll
        for (int mt = 0; mt < 2; ++mt) {
            const int x0 = wm * 32 + mt * 16 + row;
            float v;
            v = acc[mt][nt][0] * s0 + c00; v = v >= 0.f ? v : v * a0; o0[x0]     = v + d0;
            v = acc[mt][nt][1] * s1 + c01; v = v >= 0.f ? v : v * a1; o1[x0]     = v + d1;
            v = acc[mt][nt][2] * s0 + c00; v = v >= 0.f ? v : v * a0; o0[x0 + 8] = v + d0;
            v = acc[mt][nt][3] * s1 + c01; v = v >= 0.f ? v : v * a1; o1[x0 + 8] = v + d1;
        }
    }
}

// ---------------------------------------------------------------- launcher
extern "C" void kernel_launch(void* const* d_in, const int* in_sizes, int n_in,
                              void* d_out, int out_size) {
    const float* x   = (const float*)d_in[0];
    const float* wt  = (const float*)d_in[1];
    const float* mb  = (const float*)d_in[2];
    const float* pb0 = (const float*)d_in[3];
    const float* al  = (const float*)d_in[4];
    const float* pb1 = (const float*)d_in[5];
    float* out = (float*)d_out;

    cudaFuncSetAttribute(conv_kernel, cudaFuncAttributeMaxDynamicSharedMemorySize, SMEM_TOT);

    prep_kernel<<<dim3(128, NB), 256>>>(x, mb);
    wprep_kernel<<<COC, 128>>>(wt);
    conv_kernel<<<dim3(128, NB, 2), 256, SMEM_TOT>>>(out, pb0, al, pb1);
}